// round 1
// baseline (speedup 1.0000x reference)
#include <cuda_runtime.h>
#include <cuda_bf16.h>

// exp[b,q] = sum_j (-1)^{bit_{9-q}(j)} * (re[b,j]^2 + im[b,j]^2)
// BATCH = 8192, STATE_DIM = 1024, N_QUBITS = 10.
// Pure HBM-bound signed power reduction; the dense pauli_z_obs input is ignored
// (every Z_q is diagonal with +-1 entries).

#define STATE_DIM 1024
#define NQ 10

__global__ __launch_bounds__(256, 8)
void qmeas_kernel(const float* __restrict__ re,
                  const float* __restrict__ im,
                  float* __restrict__ out)
{
    const int b = blockIdx.x;
    const int t = threadIdx.x;          // 0..255, handles elements 4t..4t+3

    const float4 r4 = reinterpret_cast<const float4*>(re + (size_t)b * STATE_DIM)[t];
    const float4 i4 = reinterpret_cast<const float4*>(im + (size_t)b * STATE_DIM)[t];

    const float p0 = fmaf(r4.x, r4.x, i4.x * i4.x);
    const float p1 = fmaf(r4.y, r4.y, i4.y * i4.y);
    const float p2 = fmaf(r4.z, r4.z, i4.z * i4.z);
    const float p3 = fmaf(r4.w, r4.w, i4.w * i4.w);

    // Within the 4-element chunk, only bits 0 and 1 of j vary.
    // bit 0 -> qubit 9, bit 1 -> qubit 8.
    const float s   = (p0 + p1) + (p2 + p3);   // chunk total (used by qubits 0..7)
    const float a9  = (p0 - p1) + (p2 - p3);   // signed by bit 0
    const float a8  = (p0 + p1) - (p2 + p3);   // signed by bit 1

    float acc[NQ];
    acc[8] = a8;
    acc[9] = a9;

    const unsigned j0 = (unsigned)(t << 2);    // chunk base index; bits 2..9 constant
    #pragma unroll
    for (int q = 0; q < 8; q++) {
        const unsigned sgn = ((j0 >> (9 - q)) & 1u) << 31;  // 0 or sign-bit flip
        acc[q] = __int_as_float(__float_as_int(s) ^ sgn);
    }

    // Warp-level reduction of all 10 accumulators.
    #pragma unroll
    for (int q = 0; q < NQ; q++) {
        #pragma unroll
        for (int off = 16; off > 0; off >>= 1)
            acc[q] += __shfl_xor_sync(0xffffffffu, acc[q], off);
    }

    __shared__ float sm[8][NQ];
    const int warp = t >> 5;
    const int lane = t & 31;
    if (lane == 0) {
        #pragma unroll
        for (int q = 0; q < NQ; q++) sm[warp][q] = acc[q];
    }
    __syncthreads();

    if (t < NQ) {
        float r = 0.0f;
        #pragma unroll
        for (int w = 0; w < 8; w++) r += sm[w][t];
        out[(size_t)b * NQ + t] = r;
    }
}

extern "C" void kernel_launch(void* const* d_in, const int* in_sizes, int n_in,
                              void* d_out, int out_size)
{
    const float* state_real = (const float*)d_in[0];
    const float* state_imag = (const float*)d_in[1];
    // d_in[2] = pauli_z_obs (dense, ignored — diagonal +-1 structure exploited)

    const int batch = in_sizes[0] / STATE_DIM;   // 8192
    float* out = (float*)d_out;

    qmeas_kernel<<<batch, 256>>>(state_real, state_imag, out);
}

// round 2
// speedup vs baseline: 1.5256x; 1.5256x over previous
#include <cuda_runtime.h>
#include <cuda_bf16.h>

// exp[b,q] = sum_j (-1)^{bit_{9-q}(j)} * (re[b,j]^2 + im[b,j]^2)
// BATCH=8192, STATE_DIM=1024, NQ=10. HBM-bound signed power reduction.
// pauli_z_obs (dense) is ignored: every Z_q is diagonal +-1.
//
// Layout: CTA = 256 threads = 2 rows x 128 threads. Each thread loads 8
// contiguous elements (2 float4 per array). j bits 0..2 (qubits 9,8,7) folded
// in registers; lane bits 0..4 (j bits 3..7, qubits 6..2) via a growing
// Walsh butterfly (30 SHFLs); warp bits (j bits 8,9, qubits 1,0) via shared.

#define STATE_DIM 1024
#define NQ 10

__global__ __launch_bounds__(256, 8)
void qmeas_kernel(const float4* __restrict__ re4,
                  const float4* __restrict__ im4,
                  float* __restrict__ out)
{
    const int t = threadIdx.x;
    const int rowhalf = t >> 7;            // which of the 2 rows
    const int wt = t & 127;                // thread within row (0..127)
    const int lane = t & 31;
    const long row = (long)blockIdx.x * 2 + rowhalf;
    const long base = row * (STATE_DIM / 4) + (long)wt * 2;   // float4 index

    // Front-batched loads: 4 x LDG.128 (MLP_p1 = 4)
    const float4 r0 = re4[base];
    const float4 r1 = re4[base + 1];
    const float4 i0 = im4[base];
    const float4 i1 = im4[base + 1];

    const float p0 = fmaf(r0.x, r0.x, i0.x * i0.x);
    const float p1 = fmaf(r0.y, r0.y, i0.y * i0.y);
    const float p2 = fmaf(r0.z, r0.z, i0.z * i0.z);
    const float p3 = fmaf(r0.w, r0.w, i0.w * i0.w);
    const float p4 = fmaf(r1.x, r1.x, i1.x * i1.x);
    const float p5 = fmaf(r1.y, r1.y, i1.y * i1.y);
    const float p6 = fmaf(r1.z, r1.z, i1.z * i1.z);
    const float p7 = fmaf(r1.w, r1.w, i1.w * i1.w);

    // Fold j bits 0..2 in registers.
    // bit0 -> qubit9, bit1 -> qubit8, bit2 -> qubit7.
    const float q01 = p0 + p1, q23 = p2 + p3, q45 = p4 + p5, q67 = p6 + p7;
    const float d01 = p0 - p1, d23 = p2 - p3, d45 = p4 - p5, d67 = p6 - p7;

    float s = (q01 + q23) + (q45 + q67);
    float acc[NQ];
    acc[7] = (q01 + q23) - (q45 + q67);
    acc[8] = (q01 - q23) + (q45 - q67);
    acc[9] = (d01 + d23) + (d45 + d67);

    // Growing-accumulator Walsh butterfly over 5 lane bits.
    // Lane bit k corresponds to j bit 3+k -> qubit 6-k.
    #pragma unroll
    for (int k = 0; k < 5; k++) {
        const int off = 1 << k;
        #pragma unroll
        for (int q = 7 - k; q <= 9; q++)
            acc[q] += __shfl_xor_sync(0xffffffffu, acc[q], off);
        const float sp = __shfl_xor_sync(0xffffffffu, s, off);
        const float d = s - sp;
        const unsigned sgn = ((unsigned)(lane & off)) << (31 - k);  // sign-bit if lane bit set
        acc[6 - k] = __int_as_float(__float_as_int(d) ^ sgn);
        s += sp;
    }
    // Now s = warp total, acc[2..9] = warp-level signed sums (lane-uniform).

    // Cross-warp combine: 4 warps per row; warp bit0 -> j bit8 -> qubit1,
    // warp bit1 -> j bit9 -> qubit0.
    __shared__ float sm[2][4][12];   // [row][warpInRow][0]=s, [1..8]=acc[2..9]
    const int warpInRow = (wt >> 5);
    if (lane == 0) {
        sm[rowhalf][warpInRow][0] = s;
        #pragma unroll
        for (int q = 2; q <= 9; q++)
            sm[rowhalf][warpInRow][q - 1] = acc[q];
    }
    __syncthreads();

    if (t < 2 * NQ) {
        const int rh = t / NQ;
        const int q  = t % NQ;
        const float* w0 = sm[rh][0];
        const float* w1 = sm[rh][1];
        const float* w2 = sm[rh][2];
        const float* w3 = sm[rh][3];
        float r;
        if (q >= 2) {
            r = (w0[q - 1] + w1[q - 1]) + (w2[q - 1] + w3[q - 1]);
        } else if (q == 1) {
            r = (w0[0] - w1[0]) + (w2[0] - w3[0]);
        } else {
            r = (w0[0] + w1[0]) - (w2[0] + w3[0]);
        }
        out[((long)blockIdx.x * 2 + rh) * NQ + q] = r;
    }
}

extern "C" void kernel_launch(void* const* d_in, const int* in_sizes, int n_in,
                              void* d_out, int out_size)
{
    const float4* state_real = (const float4*)d_in[0];
    const float4* state_imag = (const float4*)d_in[1];
    // d_in[2] = pauli_z_obs (ignored)

    const int batch = in_sizes[0] / STATE_DIM;   // 8192
    float* out = (float*)d_out;

    qmeas_kernel<<<batch / 2, 256>>>(state_real, state_imag, out);
}

// round 3
// speedup vs baseline: 1.6359x; 1.0723x over previous
#include <cuda_runtime.h>
#include <cuda_bf16.h>

// exp[b,q] = sum_j (-1)^{bit_{9-q}(j)} * (re[b,j]^2 + im[b,j]^2)
// BATCH=8192, STATE_DIM=1024, NQ=10. HBM-bound signed power reduction; the
// dense pauli_z_obs input is ignored (every Z_q is diagonal +-1).
//
// One warp per row. Lane l, chunk c (0..7) handles float4 index l + 32c:
//   j = 4*(l + 32c) + e
//   e bits 0,1      -> qubits 9,8  (register fold)
//   lane bits 0..4  -> qubits 7..3 (warp Walsh butterfly, 40 SHFL / 8KB row)
//   c    bits 0..2  -> qubits 2,1,0 (register signed accumulate)
// No shared memory, no __syncthreads, warps fully independent.

#define STATE_DIM 1024
#define NQ 10

__global__ __launch_bounds__(256)
void qmeas_kernel(const float4* __restrict__ re4,
                  const float4* __restrict__ im4,
                  float* __restrict__ out)
{
    const int lane = threadIdx.x & 31;
    const int warp = threadIdx.x >> 5;
    const long row = (long)blockIdx.x * 8 + warp;
    const float4* __restrict__ rb = re4 + row * (STATE_DIM / 4);
    const float4* __restrict__ ib = im4 + row * (STATE_DIM / 4);

    float s = 0.f;
    float acc[NQ];
    acc[0] = acc[1] = acc[2] = acc[8] = acc[9] = 0.f;

    #pragma unroll
    for (int half = 0; half < 2; half++) {
        // Front-batched loads: 8 x LDG.128 in flight (MLP_p1 = 8), perfectly
        // coalesced (lane-consecutive float4s per instruction).
        float4 r[4], m[4];
        #pragma unroll
        for (int cc = 0; cc < 4; cc++) {
            const int c = half * 4 + cc;
            r[cc] = rb[lane + 32 * c];
            m[cc] = ib[lane + 32 * c];
        }
        #pragma unroll
        for (int cc = 0; cc < 4; cc++) {
            const int c = half * 4 + cc;
            const float p0 = fmaf(r[cc].x, r[cc].x, m[cc].x * m[cc].x);
            const float p1 = fmaf(r[cc].y, r[cc].y, m[cc].y * m[cc].y);
            const float p2 = fmaf(r[cc].z, r[cc].z, m[cc].z * m[cc].z);
            const float p3 = fmaf(r[cc].w, r[cc].w, m[cc].w * m[cc].w);

            const float q01 = p0 + p1, q23 = p2 + p3;
            const float d01 = p0 - p1, d23 = p2 - p3;
            const float sc = q01 + q23;

            acc[9] += d01 + d23;      // e bit0
            acc[8] += q01 - q23;      // e bit1
            s      += sc;
            acc[2] += (c & 1) ? -sc : sc;   // c bit0 -> j bit7 -> qubit2
            acc[1] += (c & 2) ? -sc : sc;   // c bit1 -> j bit8 -> qubit1
            acc[0] += (c & 4) ? -sc : sc;   // c bit2 -> j bit9 -> qubit0
        }
    }

    // Growing Walsh butterfly over 5 lane bits. Lane bit k -> j bit 2+k
    // -> qubit 7-k. Plain-reduce all live accumulators each stage; split s
    // to create the next qubit accumulator.
    #pragma unroll
    for (int k = 0; k < 5; k++) {
        const int off = 1 << k;
        acc[0] += __shfl_xor_sync(0xffffffffu, acc[0], off);
        acc[1] += __shfl_xor_sync(0xffffffffu, acc[1], off);
        acc[2] += __shfl_xor_sync(0xffffffffu, acc[2], off);
        acc[8] += __shfl_xor_sync(0xffffffffu, acc[8], off);
        acc[9] += __shfl_xor_sync(0xffffffffu, acc[9], off);
        #pragma unroll
        for (int q = 8 - k; q <= 7; q++)          // previously created accs
            acc[q] += __shfl_xor_sync(0xffffffffu, acc[q], off);

        const float sp = __shfl_xor_sync(0xffffffffu, s, off);
        const float d  = s - sp;
        const unsigned sgn = ((unsigned)(lane & off)) << (31 - k);
        acc[7 - k] = __int_as_float(__float_as_int(d) ^ sgn);
        s += sp;
    }

    // All accs are lane-uniform now; lane 0 writes 5 x STG.64 (40B, 8-aligned).
    if (lane == 0) {
        float2* o2 = reinterpret_cast<float2*>(out + row * NQ);
        o2[0] = make_float2(acc[0], acc[1]);
        o2[1] = make_float2(acc[2], acc[3]);
        o2[2] = make_float2(acc[4], acc[5]);
        o2[3] = make_float2(acc[6], acc[7]);
        o2[4] = make_float2(acc[8], acc[9]);
    }
}

extern "C" void kernel_launch(void* const* d_in, const int* in_sizes, int n_in,
                              void* d_out, int out_size)
{
    const float4* state_real = (const float4*)d_in[0];
    const float4* state_imag = (const float4*)d_in[1];
    // d_in[2] = pauli_z_obs (ignored)

    const int batch = in_sizes[0] / STATE_DIM;   // 8192
    float* out = (float*)d_out;

    qmeas_kernel<<<batch / 8, 256>>>(state_real, state_imag, out);
}

// round 4
// speedup vs baseline: 1.9125x; 1.1691x over previous
#include <cuda_runtime.h>
#include <cuda_bf16.h>

// exp[b,q] = sum_j (-1)^{bit_{9-q}(j)} * (re[b,j]^2 + im[b,j]^2)
// BATCH=8192, STATE_DIM=1024, NQ=10. pauli_z_obs ignored (diagonal +-1).
//
// One warp per row. Lane l, chunk c (0..7) handles float4 index l + 32c:
//   element bits 0,1 -> qubits 9,8  (register fold)
//   chunk   bits 0..2-> qubits 2,1,0 (register signed accumulate)
//   lane    bits 0..4-> qubits 7..3 (growing Walsh butterfly, 40 SHFL/row)
//
// The quadratic form is linear in p_j = re^2 + im^2, so re and im are
// processed in separate passes of 4 front-batched LDG.128 each -> <=32 regs
// (__launch_bounds__(256,8)) -> 8 CTAs/SM -> grid 1024 fits in ONE wave.

#define STATE_DIM 1024
#define NQ 10

__global__ __launch_bounds__(256, 8)
void qmeas_kernel(const float4* __restrict__ re4,
                  const float4* __restrict__ im4,
                  float* __restrict__ out)
{
    const int lane = threadIdx.x & 31;
    const int warp = threadIdx.x >> 5;
    const long row = (long)blockIdx.x * 8 + warp;
    const float4* __restrict__ rb = re4 + row * (STATE_DIM / 4);
    const float4* __restrict__ ib = im4 + row * (STATE_DIM / 4);

    float s = 0.f, a9 = 0.f, a8 = 0.f, a0 = 0.f, a1 = 0.f, a2 = 0.f;

    #pragma unroll
    for (int pass = 0; pass < 4; pass++) {
        const float4* __restrict__ p = (pass < 2) ? rb : ib;
        const int cb = (pass & 1) * 4;

        // Front-batched: 4 x LDG.128, lane-coalesced.
        float4 v[4];
        #pragma unroll
        for (int k = 0; k < 4; k++)
            v[k] = p[lane + 32 * (cb + k)];

        #pragma unroll
        for (int k = 0; k < 4; k++) {
            const int c = cb + k;
            const float p0 = v[k].x * v[k].x;
            const float p1 = v[k].y * v[k].y;
            const float p2 = v[k].z * v[k].z;
            const float p3 = v[k].w * v[k].w;

            const float q01 = p0 + p1, q23 = p2 + p3;
            a9 += (p0 - p1) + (p2 - p3);     // elem bit0 -> qubit9
            a8 += q01 - q23;                 // elem bit1 -> qubit8
            const float sc = q01 + q23;
            s  += sc;
            a2 += (c & 1) ? -sc : sc;        // chunk bit0 -> j bit7 -> qubit2
            a1 += (c & 2) ? -sc : sc;        // chunk bit1 -> j bit8 -> qubit1
            a0 += (c & 4) ? -sc : sc;        // chunk bit2 -> j bit9 -> qubit0
        }
    }

    float acc[NQ];
    acc[0] = a0; acc[1] = a1; acc[2] = a2; acc[8] = a8; acc[9] = a9;

    // Growing Walsh butterfly over 5 lane bits. Lane bit k -> j bit 2+k
    // -> qubit 7-k.
    #pragma unroll
    for (int k = 0; k < 5; k++) {
        const int off = 1 << k;
        acc[0] += __shfl_xor_sync(0xffffffffu, acc[0], off);
        acc[1] += __shfl_xor_sync(0xffffffffu, acc[1], off);
        acc[2] += __shfl_xor_sync(0xffffffffu, acc[2], off);
        acc[8] += __shfl_xor_sync(0xffffffffu, acc[8], off);
        acc[9] += __shfl_xor_sync(0xffffffffu, acc[9], off);
        #pragma unroll
        for (int q = 8 - k; q <= 7; q++)     // accumulators created so far
            acc[q] += __shfl_xor_sync(0xffffffffu, acc[q], off);

        const float sp = __shfl_xor_sync(0xffffffffu, s, off);
        const float d  = s - sp;
        const unsigned sgn = ((unsigned)(lane & off)) << (31 - k);
        acc[7 - k] = __int_as_float(__float_as_int(d) ^ sgn);
        s += sp;
    }

    // Lane-uniform results; lane 0 writes 5 x STG.64.
    if (lane == 0) {
        float2* o2 = reinterpret_cast<float2*>(out + row * NQ);
        o2[0] = make_float2(acc[0], acc[1]);
        o2[1] = make_float2(acc[2], acc[3]);
        o2[2] = make_float2(acc[4], acc[5]);
        o2[3] = make_float2(acc[6], acc[7]);
        o2[4] = make_float2(acc[8], acc[9]);
    }
}

extern "C" void kernel_launch(void* const* d_in, const int* in_sizes, int n_in,
                              void* d_out, int out_size)
{
    const float4* state_real = (const float4*)d_in[0];
    const float4* state_imag = (const float4*)d_in[1];
    // d_in[2] = pauli_z_obs (ignored)

    const int batch = in_sizes[0] / STATE_DIM;   // 8192
    float* out = (float*)d_out;

    qmeas_kernel<<<batch / 8, 256>>>(state_real, state_imag, out);
}

// round 6
// speedup vs baseline: 1.9524x; 1.0208x over previous
#include <cuda_runtime.h>
#include <cuda_bf16.h>

// exp[b,q] = sum_j (-1)^{bit_{9-q}(j)} * (re[b,j]^2 + im[b,j]^2)
// BATCH=8192, STATE_DIM=1024, NQ=10. pauli_z_obs ignored (diagonal +-1).
//
// One warp per TWO rows. For each row, lane l / chunk c handles float4
// index l + 32c:
//   element bits 0,1 -> qubits 9,8  (register fold)
//   chunk   bits 0..2-> qubits 2,1,0 (register signed accumulate)
//   lane    bits 0..4-> qubits 7..3 (growing Walsh butterfly)
// 128-thread CTAs with __launch_bounds__(128,8): 1024 thr/SM but 64 regs/thr,
// so ptxas can keep ~8 LDG.128 in flight across passes/rows, and both rows'
// butterflies interleave (5-stage SHFL latency paid once for two rows).

#define STATE_DIM 1024
#define NQ 10

__global__ __launch_bounds__(128, 8)
void qmeas_kernel(const float4* __restrict__ re4,
                  const float4* __restrict__ im4,
                  float* __restrict__ out)
{
    const int lane = threadIdx.x & 31;
    const int warp = threadIdx.x >> 5;
    const long gw = (long)blockIdx.x * 4 + warp;   // global warp id, 0..4095

    float sA = 0.f, sB = 0.f;
    float aA[NQ], aB[NQ];
    aA[0]=aA[1]=aA[2]=aA[8]=aA[9]=0.f;
    aB[0]=aB[1]=aB[2]=aB[8]=aB[9]=0.f;

    #pragma unroll
    for (int r = 0; r < 2; r++) {
        const long row = gw * 2 + r;
        const float4* __restrict__ rb = re4 + row * (STATE_DIM / 4);
        const float4* __restrict__ ib = im4 + row * (STATE_DIM / 4);
        float* const a = r ? aB : aA;
        float& s = r ? sB : sA;

        #pragma unroll
        for (int pass = 0; pass < 4; pass++) {
            const float4* __restrict__ p = (pass < 2) ? rb : ib;
            const int cb = (pass & 1) * 4;

            float4 v[4];
            #pragma unroll
            for (int k = 0; k < 4; k++)
                v[k] = p[lane + 32 * (cb + k)];

            #pragma unroll
            for (int k = 0; k < 4; k++) {
                const int c = cb + k;
                const float p0 = v[k].x * v[k].x;
                const float p1 = v[k].y * v[k].y;
                const float p2 = v[k].z * v[k].z;
                const float p3 = v[k].w * v[k].w;

                const float q01 = p0 + p1, q23 = p2 + p3;
                a[9] += (p0 - p1) + (p2 - p3);    // elem bit0 -> qubit9
                a[8] += q01 - q23;                // elem bit1 -> qubit8
                const float sc = q01 + q23;
                s    += sc;
                a[2] += (c & 1) ? -sc : sc;       // chunk bit0 -> qubit2
                a[1] += (c & 2) ? -sc : sc;       // chunk bit1 -> qubit1
                a[0] += (c & 4) ? -sc : sc;       // chunk bit2 -> qubit0
            }
        }
    }

    // Dual growing Walsh butterfly over 5 lane bits (lane bit k -> qubit 7-k),
    // rows A and B interleaved for ILP.
    #pragma unroll
    for (int k = 0; k < 5; k++) {
        const int off = 1 << k;
        aA[0] += __shfl_xor_sync(0xffffffffu, aA[0], off);
        aB[0] += __shfl_xor_sync(0xffffffffu, aB[0], off);
        aA[1] += __shfl_xor_sync(0xffffffffu, aA[1], off);
        aB[1] += __shfl_xor_sync(0xffffffffu, aB[1], off);
        aA[2] += __shfl_xor_sync(0xffffffffu, aA[2], off);
        aB[2] += __shfl_xor_sync(0xffffffffu, aB[2], off);
        aA[8] += __shfl_xor_sync(0xffffffffu, aA[8], off);
        aB[8] += __shfl_xor_sync(0xffffffffu, aB[8], off);
        aA[9] += __shfl_xor_sync(0xffffffffu, aA[9], off);
        aB[9] += __shfl_xor_sync(0xffffffffu, aB[9], off);
        #pragma unroll
        for (int q = 8 - k; q <= 7; q++) {        // accumulators created so far
            aA[q] += __shfl_xor_sync(0xffffffffu, aA[q], off);
            aB[q] += __shfl_xor_sync(0xffffffffu, aB[q], off);
        }
        const unsigned sgn = ((unsigned)(lane & off)) << (31 - k);

        const float spA = __shfl_xor_sync(0xffffffffu, sA, off);
        aA[7 - k] = __int_as_float(__float_as_int(sA - spA) ^ sgn);
        sA += spA;

        const float spB = __shfl_xor_sync(0xffffffffu, sB, off);
        aB[7 - k] = __int_as_float(__float_as_int(sB - spB) ^ sgn);
        sB += spB;
    }

    // Lane-uniform results; lane 0 writes both rows = 80 contiguous bytes,
    // 16B-aligned -> 5 x STG.128.
    if (lane == 0) {
        float4* o4 = reinterpret_cast<float4*>(out + gw * 2 * NQ);
        o4[0] = make_float4(aA[0], aA[1], aA[2], aA[3]);
        o4[1] = make_float4(aA[4], aA[5], aA[6], aA[7]);
        o4[2] = make_float4(aA[8], aA[9], aB[0], aB[1]);
        o4[3] = make_float4(aB[2], aB[3], aB[4], aB[5]);
        o4[4] = make_float4(aB[6], aB[7], aB[8], aB[9]);
    }
}

extern "C" void kernel_launch(void* const* d_in, const int* in_sizes, int n_in,
                              void* d_out, int out_size)
{
    const float4* state_real = (const float4*)d_in[0];
    const float4* state_imag = (const float4*)d_in[1];
    // d_in[2] = pauli_z_obs (ignored)

    const int batch = in_sizes[0] / STATE_DIM;   // 8192
    float* out = (float*)d_out;

    // 1024 CTAs x 128 threads; each of the 4096 warps handles 2 rows.
    qmeas_kernel<<<batch / 8, 128>>>(state_real, state_imag, out);
}